// round 6
// baseline (speedup 1.0000x reference)
#include <cuda_runtime.h>
#include <math.h>

#define D 256
#define O 10
#define NS 64
#define R 640   // NS*O

// ---------------- scratch ----------------
__device__ float d_W2P[D * D];     // float4 at (k4*D + t) holds W2[t][4k4..4k4+3]
__device__ float d_H1[2 * NS * D];
__device__ float d_H2[2 * NS * D];
__device__ float d_G1[2 * R * D];
__device__ float d_G2[2 * R * D];
__device__ float d_C[3][NS * NS];

// ================= K1: W2 pack (blocks 0..63) + fused forward, 4 samples/CTA =====
__global__ __launch_bounds__(256) void k1_fwd(
    const float* __restrict__ x1, const float* __restrict__ x2,
    const float* __restrict__ W1, const float* __restrict__ b1,
    const float* __restrict__ W2, const float* __restrict__ b2,
    const float* __restrict__ W3)
{
    __shared__ __align__(16) float xT[D * 4];
    __shared__ __align__(16) float h1T[D * 4];

    const int b = blockIdx.x, t = threadIdx.x;

    if (b < 64) {
        int gid = b * 256 + t;
        int k4 = gid & 63, tw = gid >> 6;
        float4 v = *(const float4*)&W2[tw * D + k4 * 4];
        *(float4*)&d_W2P[(k4 * D + tw) * 4] = v;
        return;
    }

    const int s0 = (b - 64) * 4;

#pragma unroll
    for (int s = 0; s < 4; s++) {
        int sg = s0 + s;
        const float* xr = (sg < NS) ? (x1 + sg * D) : (x2 + (sg - NS) * D);
        xT[t * 4 + s] = xr[t];
    }
    __syncthreads();

    float bb = b1[t];
    float a0 = bb, a1 = bb, a2 = bb, a3 = bb;
#pragma unroll 8
    for (int i = 0; i < D; i++) {
        float w = W1[i * D + t];
        float4 xv = *(const float4*)&xT[i * 4];
        a0 += xv.x * w; a1 += xv.y * w; a2 += xv.z * w; a3 += xv.w * w;
    }
    float h10 = tanhf(a0), h11 = tanhf(a1), h12 = tanhf(a2), h13 = tanhf(a3);
    d_H1[(s0 + 0) * D + t] = h10;
    d_H1[(s0 + 1) * D + t] = h11;
    d_H1[(s0 + 2) * D + t] = h12;
    d_H1[(s0 + 3) * D + t] = h13;
    h1T[t * 4 + 0] = h10; h1T[t * 4 + 1] = h11;
    h1T[t * 4 + 2] = h12; h1T[t * 4 + 3] = h13;
    __syncthreads();

    bb = b2[t];
    a0 = bb; a1 = bb; a2 = bb; a3 = bb;
#pragma unroll 8
    for (int i = 0; i < D; i++) {
        float w = W2[i * D + t];
        float4 hv = *(const float4*)&h1T[i * 4];
        a0 += hv.x * w; a1 += hv.y * w; a2 += hv.z * w; a3 += hv.w * w;
    }
    float h20 = tanhf(a0), h21 = tanhf(a1), h22 = tanhf(a2), h23 = tanhf(a3);
    d_H2[(s0 + 0) * D + t] = h20;
    d_H2[(s0 + 1) * D + t] = h21;
    d_H2[(s0 + 2) * D + t] = h22;
    d_H2[(s0 + 3) * D + t] = h23;
    float t20 = 1.f - h20 * h20, t21 = 1.f - h21 * h21;
    float t22 = 1.f - h22 * h22, t23 = 1.f - h23 * h23;

#pragma unroll
    for (int a = 0; a < O; a++) {
        float w3 = W3[t * O + a];
        d_G2[((s0 + 0) * O + a) * D + t] = w3 * t20;
        d_G2[((s0 + 1) * O + a) * D + t] = w3 * t21;
        d_G2[((s0 + 2) * O + a) * D + t] = w3 * t22;
        d_G2[((s0 + 3) * O + a) * D + t] = w3 * t23;
    }
}

// ================= K2: G1 backward (blocks 0..255) + pairwise dots (256..319) =====
__global__ __launch_bounds__(256) void k2_bwd_dots(
    const float* __restrict__ x1, const float* __restrict__ x2)
{
    __shared__ float sm[5 * D];
    const int b = blockIdx.x, t = threadIdx.x;

    if (b < 256) {
        const int s = b >> 1, half = b & 1;
#pragma unroll
        for (int j = 0; j < 5; j++)
            sm[j * D + t] = d_G2[(s * O + half * 5 + j) * D + t];
        float h1 = d_H1[s * D + t];
        float t1 = 1.0f - h1 * h1;
        __syncthreads();

        float a0 = 0.f, a1 = 0.f, a2 = 0.f, a3 = 0.f, a4 = 0.f;
#pragma unroll 4
        for (int k4 = 0; k4 < 64; k4++) {
            float4 w  = *(const float4*)&d_W2P[(k4 * D + t) * 4];
            float4 g0 = *(const float4*)&sm[0 * D + k4 * 4];
            float4 g1 = *(const float4*)&sm[1 * D + k4 * 4];
            float4 g2 = *(const float4*)&sm[2 * D + k4 * 4];
            float4 g3 = *(const float4*)&sm[3 * D + k4 * 4];
            float4 g4 = *(const float4*)&sm[4 * D + k4 * 4];
            a0 += w.x * g0.x + w.y * g0.y + w.z * g0.z + w.w * g0.w;
            a1 += w.x * g1.x + w.y * g1.y + w.z * g1.z + w.w * g1.w;
            a2 += w.x * g2.x + w.y * g2.y + w.z * g2.z + w.w * g2.w;
            a3 += w.x * g3.x + w.y * g3.y + w.z * g3.z + w.w * g3.w;
            a4 += w.x * g4.x + w.y * g4.y + w.z * g4.z + w.w * g4.w;
        }
        const int base = (s * O + half * 5) * D + t;
        d_G1[base + 0 * D] = t1 * a0;
        d_G1[base + 1 * D] = t1 * a1;
        d_G1[base + 2 * D] = t1 * a2;
        d_G1[base + 3 * D] = t1 * a3;
        d_G1[base + 4 * D] = t1 * a4;
        return;
    }

    const int n = b - 256;
    float* xa  = sm;
    float* h1a = sm + D;
    float* h2a = sm + 2 * D;
    xa[t]  = x1[n * D + t];
    h1a[t] = d_H1[n * D + t];
    h2a[t] = d_H2[n * D + t];
    __syncthreads();

    const int warp = t >> 5, lane = t & 31;
#pragma unroll
    for (int mi = 0; mi < 8; mi++) {
        int m = warp * 8 + mi;
        const float* x2r = x2 + m * D;
        const float* h1r = d_H1 + (NS + m) * D;
        const float* h2r = d_H2 + (NS + m) * D;
        float s0 = 0.f, s1 = 0.f, s2 = 0.f;
#pragma unroll
        for (int k = lane; k < D; k += 32) {
            s0 += xa[k]  * x2r[k];
            s1 += h1a[k] * h1r[k];
            s2 += h2a[k] * h2r[k];
        }
#pragma unroll
        for (int off = 16; off > 0; off >>= 1) {
            s0 += __shfl_down_sync(0xffffffffu, s0, off);
            s1 += __shfl_down_sync(0xffffffffu, s1, off);
            s2 += __shfl_down_sync(0xffffffffu, s2, off);
        }
        if (lane == 0) {
            d_C[0][n * NS + m] = s0 + 1.0f;
            d_C[1][n * NS + m] = s1 + 1.0f;
            d_C[2][n * NS + m] = s2 + 1.0f;
        }
    }
}

// ================= K3: fused pair-GEMMs (both layers, K=512) + NTK combine ========
// 64x64 tile, 256 threads, 4x4 micro x 2 layers, double-buffered 16-deep stages,
// grid (10,10) = 100 CTAs -> single wave.
__global__ __launch_bounds__(256) void gemm_fused(float* __restrict__ out) {
    __shared__ __align__(16) float As[2][16][68];
    __shared__ __align__(16) float Bs[2][16][68];

    const int tid = threadIdx.x;
    const int tx = tid & 15, ty = tid >> 4;
    const int r0 = blockIdx.y * 64, c0 = blockIdx.x * 64;
    const int lrow = tid >> 2;          // 0..63
    const int lk   = (tid & 3) * 4;     // 0,4,8,12

    float4 a4, b4;
    float acc0[4][4] = {};
    float acc1[4][4] = {};

#define GF_LDG(st) {                                                          \
    const float* G = ((st) < 16) ? d_G1 : d_G2;                               \
    const int kc = ((st) & 15) * 16;                                          \
    a4 = *(const float4*)&G[(r0 + lrow) * D + kc + lk];                       \
    b4 = *(const float4*)&G[(R + c0 + lrow) * D + kc + lk];                   \
}
#define GF_STS(buf) {                                                         \
    As[buf][lk + 0][lrow] = a4.x; As[buf][lk + 1][lrow] = a4.y;               \
    As[buf][lk + 2][lrow] = a4.z; As[buf][lk + 3][lrow] = a4.w;               \
    Bs[buf][lk + 0][lrow] = b4.x; Bs[buf][lk + 1][lrow] = b4.y;               \
    Bs[buf][lk + 2][lrow] = b4.z; Bs[buf][lk + 3][lrow] = b4.w;               \
}
#define GF_COMP(cur, ACC) {                                                   \
    _Pragma("unroll")                                                         \
    for (int k = 0; k < 16; k++) {                                            \
        float4 av = *(const float4*)&As[cur][k][ty * 4];                      \
        float4 bv = *(const float4*)&Bs[cur][k][tx * 4];                      \
        float a[4] = {av.x, av.y, av.z, av.w};                                \
        float bb[4] = {bv.x, bv.y, bv.z, bv.w};                               \
        _Pragma("unroll")                                                     \
        for (int i = 0; i < 4; i++)                                           \
            _Pragma("unroll")                                                 \
            for (int j = 0; j < 4; j++)                                       \
                ACC[i][j] += a[i] * bb[j];                                    \
    } }

    GF_LDG(0); GF_STS(0); __syncthreads();

#pragma unroll 1
    for (int st = 0; st < 16; st++) {
        const int cur = st & 1;
        GF_LDG(st + 1);
        GF_COMP(cur, acc0);
        GF_STS(cur ^ 1);
        __syncthreads();
    }
#pragma unroll 1
    for (int st = 16; st < 32; st++) {
        const int cur = st & 1;
        if (st < 31) GF_LDG(st + 1);
        GF_COMP(cur, acc1);
        if (st < 31) { GF_STS(cur ^ 1); __syncthreads(); }
    }
#undef GF_LDG
#undef GF_STS
#undef GF_COMP

    // ---- epilogue: out[n,m,a,b] = C0*P0 + C1*P1 + (a==b)*C2 ----
#pragma unroll
    for (int i = 0; i < 4; i++) {
        int row = r0 + ty * 4 + i;            // n*10 + a
        int n = row / 10, a = row - n * 10;
#pragma unroll
        for (int j = 0; j < 4; j++) {
            int col = c0 + tx * 4 + j;        // m*10 + b
            int m = col / 10, bb = col - m * 10;
            int ci = n * NS + m;
            float v = d_C[0][ci] * acc0[i][j] + d_C[1][ci] * acc1[i][j];
            if (a == bb) v += d_C[2][ci];
            out[(n * NS + m) * 100 + a * 10 + bb] = v;
        }
    }
}

// ---------------- launcher ----------------
extern "C" void kernel_launch(void* const* d_in, const int* in_sizes, int n_in,
                              void* d_out, int out_size) {
    const float* x1 = (const float*)d_in[0];
    const float* x2 = (const float*)d_in[1];
    const float* W1 = (const float*)d_in[2];
    const float* b1 = (const float*)d_in[3];
    const float* W2 = (const float*)d_in[4];
    const float* b2 = (const float*)d_in[5];
    const float* W3 = (const float*)d_in[6];
    float* out = (float*)d_out;

    k1_fwd<<<96, 256>>>(x1, x2, W1, b1, W2, b2, W3);
    k2_bwd_dots<<<320, 256>>>(x1, x2);
    gemm_fused<<<dim3(10, 10), 256>>>(out);
}

// round 7
// speedup vs baseline: 1.1188x; 1.1188x over previous
#include <cuda_runtime.h>
#include <math.h>

#define D 256
#define O 10
#define NS 64
#define R 640   // NS*O

// ---------------- scratch ----------------
__device__ float d_W2P[D * D];     // float4 at (k4*D + t) holds W2[t][4k4..4k4+3]
__device__ float d_H1[2 * NS * D];
__device__ float d_H2[2 * NS * D];
__device__ float d_G1[2 * R * D];
__device__ float d_G2[2 * R * D];
__device__ float d_P[2][R * R];
__device__ float d_C[3][NS * NS];

// ================= K1: W2 pack (blocks 0..63) + fused forward, 2 samples/CTA =====
// Forward blocks: t = output unit. 4 independent FMA chains (2 samples x 2 k-subaccs),
// k-loop step 2 with unroll 16 -> 32 LDGs in flight per warp (hides L2 latency).
__global__ __launch_bounds__(256) void k1_fwd(
    const float* __restrict__ x1, const float* __restrict__ x2,
    const float* __restrict__ W1, const float* __restrict__ b1,
    const float* __restrict__ W2, const float* __restrict__ b2,
    const float* __restrict__ W3)
{
    __shared__ __align__(8) float2 xT[D];
    __shared__ __align__(8) float2 h1T[D];

    const int b = blockIdx.x, t = threadIdx.x;

    if (b < 64) {
        int gid = b * 256 + t;
        int k4 = gid & 63, tw = gid >> 6;
        float4 v = *(const float4*)&W2[tw * D + k4 * 4];
        *(float4*)&d_W2P[(k4 * D + tw) * 4] = v;
        return;
    }

    const int s0 = (b - 64) * 2;
    const float* xr0 = (s0 < NS) ? (x1 + s0 * D) : (x2 + (s0 - NS) * D);
    const float* xr1 = (s0 + 1 < NS) ? (x1 + (s0 + 1) * D) : (x2 + (s0 + 1 - NS) * D);
    xT[t] = make_float2(xr0[t], xr1[t]);
    __syncthreads();

    // ---- layer 1 ----
    float bias = b1[t];
    float a0 = bias, a1 = 0.f;   // sample 0: two k-subaccumulators
    float c0 = bias, c1 = 0.f;   // sample 1
#pragma unroll 16
    for (int i = 0; i < D; i += 2) {
        float w0 = W1[i * D + t];
        float w1 = W1[(i + 1) * D + t];
        float2 x0 = xT[i];
        float2 x1v = xT[i + 1];
        a0 += x0.x * w0;  c0 += x0.y * w0;
        a1 += x1v.x * w1; c1 += x1v.y * w1;
    }
    float h1_0 = tanhf(a0 + a1), h1_1 = tanhf(c0 + c1);
    d_H1[(s0 + 0) * D + t] = h1_0;
    d_H1[(s0 + 1) * D + t] = h1_1;
    h1T[t] = make_float2(h1_0, h1_1);
    __syncthreads();

    // ---- layer 2 ----
    bias = b2[t];
    a0 = bias; a1 = 0.f; c0 = bias; c1 = 0.f;
#pragma unroll 16
    for (int i = 0; i < D; i += 2) {
        float w0 = W2[i * D + t];
        float w1 = W2[(i + 1) * D + t];
        float2 h0 = h1T[i];
        float2 h1v = h1T[i + 1];
        a0 += h0.x * w0;  c0 += h0.y * w0;
        a1 += h1v.x * w1; c1 += h1v.y * w1;
    }
    float h2_0 = tanhf(a0 + a1), h2_1 = tanhf(c0 + c1);
    d_H2[(s0 + 0) * D + t] = h2_0;
    d_H2[(s0 + 1) * D + t] = h2_1;
    float t20 = 1.f - h2_0 * h2_0, t21 = 1.f - h2_1 * h2_1;

    // ---- G2[s,a,t] = W3[t,a] * (1 - h2^2) ----
#pragma unroll
    for (int a = 0; a < O; a++) {
        float w3 = W3[t * O + a];
        d_G2[((s0 + 0) * O + a) * D + t] = w3 * t20;
        d_G2[((s0 + 1) * O + a) * D + t] = w3 * t21;
    }
}

// ================= K2: G1 backward (blocks 0..255) + pairwise dots (256..319) =====
__global__ __launch_bounds__(256) void k2_bwd_dots(
    const float* __restrict__ x1, const float* __restrict__ x2)
{
    __shared__ float sm[5 * D];
    const int b = blockIdx.x, t = threadIdx.x;

    if (b < 256) {
        const int s = b >> 1, half = b & 1;
#pragma unroll
        for (int j = 0; j < 5; j++)
            sm[j * D + t] = d_G2[(s * O + half * 5 + j) * D + t];
        float h1 = d_H1[s * D + t];
        float t1 = 1.0f - h1 * h1;
        __syncthreads();

        float a0 = 0.f, a1 = 0.f, a2 = 0.f, a3 = 0.f, a4 = 0.f;
#pragma unroll 4
        for (int k4 = 0; k4 < 64; k4++) {
            float4 w  = *(const float4*)&d_W2P[(k4 * D + t) * 4];
            float4 g0 = *(const float4*)&sm[0 * D + k4 * 4];
            float4 g1 = *(const float4*)&sm[1 * D + k4 * 4];
            float4 g2 = *(const float4*)&sm[2 * D + k4 * 4];
            float4 g3 = *(const float4*)&sm[3 * D + k4 * 4];
            float4 g4 = *(const float4*)&sm[4 * D + k4 * 4];
            a0 += w.x * g0.x + w.y * g0.y + w.z * g0.z + w.w * g0.w;
            a1 += w.x * g1.x + w.y * g1.y + w.z * g1.z + w.w * g1.w;
            a2 += w.x * g2.x + w.y * g2.y + w.z * g2.z + w.w * g2.w;
            a3 += w.x * g3.x + w.y * g3.y + w.z * g3.z + w.w * g3.w;
            a4 += w.x * g4.x + w.y * g4.y + w.z * g4.z + w.w * g4.w;
        }
        const int base = (s * O + half * 5) * D + t;
        d_G1[base + 0 * D] = t1 * a0;
        d_G1[base + 1 * D] = t1 * a1;
        d_G1[base + 2 * D] = t1 * a2;
        d_G1[base + 3 * D] = t1 * a3;
        d_G1[base + 4 * D] = t1 * a4;
        return;
    }

    const int n = b - 256;
    float* xa  = sm;
    float* h1a = sm + D;
    float* h2a = sm + 2 * D;
    xa[t]  = x1[n * D + t];
    h1a[t] = d_H1[n * D + t];
    h2a[t] = d_H2[n * D + t];
    __syncthreads();

    const int warp = t >> 5, lane = t & 31;
#pragma unroll
    for (int mi = 0; mi < 8; mi++) {
        int m = warp * 8 + mi;
        const float* x2r = x2 + m * D;
        const float* h1r = d_H1 + (NS + m) * D;
        const float* h2r = d_H2 + (NS + m) * D;
        float s0 = 0.f, s1 = 0.f, s2 = 0.f;
#pragma unroll
        for (int k = lane; k < D; k += 32) {
            s0 += xa[k]  * x2r[k];
            s1 += h1a[k] * h1r[k];
            s2 += h2a[k] * h2r[k];
        }
#pragma unroll
        for (int off = 16; off > 0; off >>= 1) {
            s0 += __shfl_down_sync(0xffffffffu, s0, off);
            s1 += __shfl_down_sync(0xffffffffu, s1, off);
            s2 += __shfl_down_sync(0xffffffffu, s2, off);
        }
        if (lane == 0) {
            d_C[0][n * NS + m] = s0 + 1.0f;
            d_C[1][n * NS + m] = s1 + 1.0f;
            d_C[2][n * NS + m] = s2 + 1.0f;
        }
    }
}

// ================= K3: P_l = G_l1[640,256] @ G_l2[640,256]^T  (double-buffered) ====
__global__ __launch_bounds__(256) void gemm64() {
    const int layer = blockIdx.z;
    const float* G = (layer == 0) ? d_G1 : d_G2;
    const float* A = G;
    const float* B = G + R * D;
    float* P = d_P[layer];

    __shared__ __align__(16) float As[2][16][68];
    __shared__ __align__(16) float Bs[2][16][68];

    const int tid = threadIdx.x;
    const int tx = tid & 15, ty = tid >> 4;
    const int r0 = blockIdx.y * 64, c0 = blockIdx.x * 64;
    const int lrow = tid >> 2;
    const int lk   = (tid & 3) * 4;

    float4 a4, b4;
    float acc[4][4] = {};

#define G64_LDG(kc) {                                                         \
    a4 = *(const float4*)&A[(r0 + lrow) * D + (kc) + lk];                     \
    b4 = *(const float4*)&B[(c0 + lrow) * D + (kc) + lk];                     \
}
#define G64_STS(buf) {                                                        \
    As[buf][lk + 0][lrow] = a4.x; As[buf][lk + 1][lrow] = a4.y;               \
    As[buf][lk + 2][lrow] = a4.z; As[buf][lk + 3][lrow] = a4.w;               \
    Bs[buf][lk + 0][lrow] = b4.x; Bs[buf][lk + 1][lrow] = b4.y;               \
    Bs[buf][lk + 2][lrow] = b4.z; Bs[buf][lk + 3][lrow] = b4.w;               \
}

    G64_LDG(0); G64_STS(0); __syncthreads();

#pragma unroll 1
    for (int st = 0; st < 16; st++) {
        const int cur = st & 1;
        if (st < 15) G64_LDG((st + 1) * 16);
#pragma unroll
        for (int k = 0; k < 16; k++) {
            float4 av = *(const float4*)&As[cur][k][ty * 4];
            float4 bv = *(const float4*)&Bs[cur][k][tx * 4];
            float a[4] = {av.x, av.y, av.z, av.w};
            float bb[4] = {bv.x, bv.y, bv.z, bv.w};
#pragma unroll
            for (int i = 0; i < 4; i++)
#pragma unroll
                for (int j = 0; j < 4; j++)
                    acc[i][j] += a[i] * bb[j];
        }
        if (st < 15) { G64_STS(cur ^ 1); __syncthreads(); }
    }
#undef G64_LDG
#undef G64_STS

#pragma unroll
    for (int i = 0; i < 4; i++) {
        float4 v = make_float4(acc[i][0], acc[i][1], acc[i][2], acc[i][3]);
        *(float4*)&P[(r0 + ty * 4 + i) * R + c0 + tx * 4] = v;
    }
}

// ================= K4: combine ====================================================
__global__ __launch_bounds__(256) void combine_kernel(float* __restrict__ out) {
    int idx = blockIdx.x * 256 + threadIdx.x;
    if (idx >= NS * NS * O * O) return;
    int n  = idx / (NS * O * O);
    int r  = idx % (NS * O * O);
    int m  = r / (O * O);
    int ab = r % (O * O);
    int a = ab / O, b = ab % O;
    int pidx = (n * O + a) * R + (m * O + b);
    int cidx = n * NS + m;
    float v = d_C[0][cidx] * d_P[0][pidx]
            + d_C[1][cidx] * d_P[1][pidx];
    if (a == b) v += d_C[2][cidx];
    out[idx] = v;
}

// ---------------- launcher ----------------
extern "C" void kernel_launch(void* const* d_in, const int* in_sizes, int n_in,
                              void* d_out, int out_size) {
    const float* x1 = (const float*)d_in[0];
    const float* x2 = (const float*)d_in[1];
    const float* W1 = (const float*)d_in[2];
    const float* b1 = (const float*)d_in[3];
    const float* W2 = (const float*)d_in[4];
    const float* b2 = (const float*)d_in[5];
    const float* W3 = (const float*)d_in[6];
    float* out = (float*)d_out;

    k1_fwd<<<128, 256>>>(x1, x2, W1, b1, W2, b2, W3);
    k2_bwd_dots<<<320, 256>>>(x1, x2);
    gemm64<<<dim3(10, 10, 2), 256>>>();
    combine_kernel<<<(NS * NS * O * O + 255) / 256, 256>>>(out);
}